// round 1
// baseline (speedup 1.0000x reference)
#include <cuda_runtime.h>

// ---------------- problem constants ----------------
#define B_    8
#define H_    64
#define W_    64
#define CIN   64
#define COUT  128
#define NB    6                 // spline bases per input
#define NF    7                 // features per input channel (silu + 6 bases)
#define FDIM  (CIN*NF)          // 448
#define HP    (H_+2)            // padded
#define WP    (W_+2)
#define KDIM  (9*FDIM)          // 4032
#define NPIX  (B_*H_*W_)        // 32768
#define PATCH 576               // CIN*9

// Scratch (device globals: allowed; no runtime allocation)
__device__ float g_F[(size_t)B_*HP*WP*FDIM];   // ~62.4 MB feature map (padded)
__device__ float g_W[(size_t)KDIM*COUT];       // 2 MB packed weights [k][o]

// ---------------- kernel 1: features ----------------
// One thread per (b, hp, wp, c). Out-of-bounds pixels use v=0 exactly like the
// reference (zero-padded patches fed through silu + b-splines).
__global__ void feat_kernel(const float* __restrict__ x)
{
    int idx = blockIdx.x * blockDim.x + threadIdx.x;
    int c  = idx & (CIN-1);
    int r  = idx >> 6;
    int wp = r % WP; r /= WP;
    int hp = r % HP;
    int b  = r / HP;

    int h = hp - 1, w = wp - 1;
    float v = 0.0f;
    if (h >= 0 && h < H_ && w >= 0 && w < W_)
        v = x[(((size_t)b*H_ + h)*W_ + w)*CIN + c];

    // knots: grid[j] = (j-3)*h + GRID_MIN, h = 2/3, j = 0..9
    const float hh = 2.0f / 3.0f;
    float g[10];
    #pragma unroll
    for (int j = 0; j < 10; j++) g[j] = (float)(j - 3) * hh - 1.0f;

    // Cox–de Boor recursion, exactly as the reference
    float bas[9];
    #pragma unroll
    for (int i = 0; i < 9; i++)
        bas[i] = (v >= g[i] && v < g[i+1]) ? 1.0f : 0.0f;
    #pragma unroll
    for (int p = 1; p <= 3; p++) {
        #pragma unroll
        for (int i = 0; i < 9 - p; i++) {
            float l  = (v - g[i])     / (g[i+p]   - g[i]);
            float rr = (g[i+p+1] - v) / (g[i+p+1] - g[i+1]);
            bas[i] = l * bas[i] + rr * bas[i+1];
        }
    }

    float s = v / (1.0f + expf(-v));   // silu

    size_t base = (((size_t)b*HP + hp)*WP + wp)*FDIM + c;
    g_F[base] = s;
    #pragma unroll
    for (int m = 0; m < NB; m++)
        g_F[base + (size_t)(m+1)*CIN] = bas[m];
}

// ---------------- kernel 2: weight repack ----------------
// g_W[k][o], k = t*448 + f*64 + c, patch index i = c*9 + t
// (conv_general_dilated_patches orders the patch channel-major: (c, ky, kx)).
__global__ void pack_kernel(const float* __restrict__ base_w,
                            const float* __restrict__ spline_w)
{
    int idx = blockIdx.x * blockDim.x + threadIdx.x;   // k*128 + o
    int o = idx & 127;
    int k = idx >> 7;
    int t = k / FDIM;
    int r = k - t * FDIM;
    int f = r >> 6;
    int c = r & 63;
    int i = c * 9 + t;
    float wv;
    if (f == 0) wv = base_w[(size_t)o * PATCH + i];
    else        wv = spline_w[((size_t)o * PATCH + i) * 6 + (f - 1)];
    g_W[idx] = wv;
}

// ---------------- kernel 3: GEMM (fp32, f32x2 packed FMA) ----------------
__device__ __forceinline__ unsigned long long pack2(float x) {
    unsigned long long r;
    asm("mov.b64 %0, {%1, %1};" : "=l"(r) : "f"(x));
    return r;
}
__device__ __forceinline__ void ffma2(unsigned long long& d,
                                      unsigned long long a,
                                      unsigned long long b) {
    asm("fma.rn.f32x2 %0, %1, %2, %0;" : "+l"(d) : "l"(a), "l"(b));
}
__device__ __forceinline__ float2 unpk(unsigned long long v) {
    float2 r;
    asm("mov.b64 {%0, %1}, %2;" : "=f"(r.x), "=f"(r.y) : "l"(v));
    return r;
}

#define BM 128
#define BN 128
#define BK 16
#define KSTEPS (KDIM / BK)   // 252

__global__ void __launch_bounds__(256, 1)
gemm_kernel(const float* __restrict__ bias, float* __restrict__ out)
{
    __shared__ float As[BK][BM];
    __shared__ float Bs[BK][BN];

    const int tid = threadIdx.x;
    const int tx  = tid & 15;          // 16 col-groups
    const int ty  = tid >> 4;          // 16 row-groups
    const int txc = tx << 2;           // col fragment base: cols [txc, txc+4) and [64+txc, ...)

    // ---- A (feature) global-load assignment: row rA, 8 consecutive k-values
    const int rA = tid >> 1;
    const int cA = (tid & 1) << 3;
    {
        // nothing
    }
    const int n  = blockIdx.x * BM + rA;
    const int b  = n >> 12;
    const int h  = (n >> 6) & 63;
    const int w  = n & 63;
    const float* aBase = g_F + (((size_t)b*HP + h)*WP + w)*FDIM;

    // ---- B (weight) global-load assignment
    const int rB = tid >> 4;           // 0..15 (k row)
    const int cB = (tid & 15) << 3;    // 8 consecutive out-channels

    unsigned long long acc[8][4];
    #pragma unroll
    for (int i = 0; i < 8; i++)
        #pragma unroll
        for (int j = 0; j < 4; j++) acc[i][j] = 0ull;

    // ---- prologue: load tile kc=0 (offset 0: t=0,f=0,c0=0)
    {
        const float4* pa = (const float4*)(aBase + cA);
        float4 a0 = pa[0], a1 = pa[1];
        const float4* pb = (const float4*)(g_W + (size_t)rB*COUT + cB);
        float4 b0 = pb[0], b1 = pb[1];
        #pragma unroll
        for (int j = 0; j < 4; j++) {
            As[cA + j][rA]     = ((const float*)&a0)[j];
            As[cA + 4 + j][rA] = ((const float*)&a1)[j];
        }
        *(float4*)&Bs[rB][cB]     = b0;
        *(float4*)&Bs[rB][cB + 4] = b1;
    }
    __syncthreads();

    for (int kc = 0; kc < KSTEPS; kc++) {
        float4 na0, na1, nb0, nb1;
        const bool more = (kc + 1 < KSTEPS);
        if (more) {
            const int kn = kc + 1;
            const int t  = kn / 28;          // tap 0..8
            const int r  = kn - t * 28;
            const int f  = r >> 2;           // feature 0..6
            const int c0 = (r & 3) << 4;     // channel chunk
            const int ky = t / 3;
            const int kx = t - ky * 3;
            const int off = (ky * WP + kx) * FDIM + f * 64 + c0;
            const float4* pa = (const float4*)(aBase + off + cA);
            na0 = pa[0]; na1 = pa[1];
            const float4* pb = (const float4*)(g_W + ((size_t)kn*BK + rB)*COUT + cB);
            nb0 = pb[0]; nb1 = pb[1];
        }

        #pragma unroll
        for (int k = 0; k < BK; k++) {
            float av[8];
            *(float4*)&av[0] = *(const float4*)&As[k][ty << 3];
            *(float4*)&av[4] = *(const float4*)&As[k][(ty << 3) + 4];
            const ulonglong2 bb0 = *(const ulonglong2*)&Bs[k][txc];
            const ulonglong2 bb1 = *(const ulonglong2*)&Bs[k][64 + txc];
            const unsigned long long bv[4] = {bb0.x, bb0.y, bb1.x, bb1.y};
            #pragma unroll
            for (int i = 0; i < 8; i++) {
                const unsigned long long ap = pack2(av[i]);
                #pragma unroll
                for (int j = 0; j < 4; j++) ffma2(acc[i][j], ap, bv[j]);
            }
        }
        __syncthreads();
        if (more) {
            #pragma unroll
            for (int j = 0; j < 4; j++) {
                As[cA + j][rA]     = ((const float*)&na0)[j];
                As[cA + 4 + j][rA] = ((const float*)&na1)[j];
            }
            *(float4*)&Bs[rB][cB]     = nb0;
            *(float4*)&Bs[rB][cB + 4] = nb1;
        }
        __syncthreads();
    }

    // ---- epilogue: + bias, store
    float bvals[8];
    *(float4*)&bvals[0] = *(const float4*)(bias + txc);
    *(float4*)&bvals[4] = *(const float4*)(bias + 64 + txc);

    const size_t outRow = (size_t)blockIdx.x * BM + (ty << 3);
    #pragma unroll
    for (int i = 0; i < 8; i++) {
        float2 p0 = unpk(acc[i][0]), p1 = unpk(acc[i][1]);
        float2 p2 = unpk(acc[i][2]), p3 = unpk(acc[i][3]);
        float4 o0, o1;
        o0.x = p0.x + bvals[0]; o0.y = p0.y + bvals[1];
        o0.z = p1.x + bvals[2]; o0.w = p1.y + bvals[3];
        o1.x = p2.x + bvals[4]; o1.y = p2.y + bvals[5];
        o1.z = p3.x + bvals[6]; o1.w = p3.y + bvals[7];
        float* po = out + (outRow + i) * COUT + txc;
        *(float4*)po        = o0;
        *(float4*)(po + 64) = o1;
    }
}

// ---------------- launch ----------------
extern "C" void kernel_launch(void* const* d_in, const int* in_sizes, int n_in,
                              void* d_out, int out_size)
{
    // Identify inputs robustly by element count (all distinct).
    const float *x = nullptr, *bw = nullptr, *sw = nullptr, *bs = nullptr;
    for (int i = 0; i < n_in; i++) {
        switch (in_sizes[i]) {
            case B_*H_*W_*CIN:   x  = (const float*)d_in[i]; break;  // 2097152
            case COUT*PATCH:     bw = (const float*)d_in[i]; break;  // 73728
            case COUT*PATCH*NB:  sw = (const float*)d_in[i]; break;  // 442368
            case COUT:           bs = (const float*)d_in[i]; break;  // 128
        }
    }
    float* out = (float*)d_out;

    const int featTotal = B_ * HP * WP * CIN;          // 2,230,272 (divisible by 256)
    feat_kernel<<<featTotal / 256, 256>>>(x);

    const int packTotal = KDIM * COUT;                 // 516,096 (divisible by 256)
    pack_kernel<<<packTotal / 256, 256>>>(bw, sw);

    gemm_kernel<<<NPIX / BM, 256>>>(bs, out);
}

// round 3
// speedup vs baseline: 1.9719x; 1.9719x over previous
#include <cuda_runtime.h>
#include <cuda_bf16.h>
#include <cstdint>

// ---------------- problem constants ----------------
#define B_     8
#define CIN    64
#define COUT   128
#define HP     66
#define WP     66
#define FDIM   448               // 64 ch * 7 features
#define KDIM   4032              // 9 taps * 448
#define NPIX   32768
#define PATCH  576
#define NCHUNK 126               // K chunks of 32

// ---------------- scratch (device globals) ----------------
__device__ __nv_bfloat16 g_Fh[(size_t)B_*HP*WP*FDIM];   // 31.2 MB
__device__ __nv_bfloat16 g_Fl[(size_t)B_*HP*WP*FDIM];   // 31.2 MB
__device__ __nv_bfloat16 g_Wh[(size_t)COUT*KDIM];       // 1 MB  [o][k]
__device__ __nv_bfloat16 g_Wl[(size_t)COUT*KDIM];       // 1 MB

// ---------------- PTX helpers ----------------
__device__ __forceinline__ uint32_t smem_u32(const void* p) {
    uint32_t a;
    asm("{ .reg .u64 t; cvta.to.shared.u64 t, %1; cvt.u32.u64 %0, t; }"
        : "=r"(a) : "l"(p));
    return a;
}
__device__ __forceinline__ void cpasync16(uint32_t sa, const void* g) {
    asm volatile("cp.async.cg.shared.global [%0], [%1], 16;"
                 :: "r"(sa), "l"(g) : "memory");
}
__device__ __forceinline__ void cp_commit() {
    asm volatile("cp.async.commit_group;" ::: "memory");
}
__device__ __forceinline__ void cp_wait2() {
    asm volatile("cp.async.wait_group 2;" ::: "memory");
}
__device__ __forceinline__ void ldsm4(uint32_t* r, uint32_t addr) {
    asm volatile("ldmatrix.sync.aligned.m8n8.x4.shared.b16 {%0,%1,%2,%3}, [%4];"
                 : "=r"(r[0]), "=r"(r[1]), "=r"(r[2]), "=r"(r[3]) : "r"(addr));
}
__device__ __forceinline__ void mma16816(float* d, const uint32_t* a, const uint32_t* b) {
    asm volatile(
        "mma.sync.aligned.m16n8k16.row.col.f32.bf16.bf16.f32 "
        "{%0,%1,%2,%3}, {%4,%5,%6,%7}, {%8,%9}, {%0,%1,%2,%3};"
        : "+f"(d[0]), "+f"(d[1]), "+f"(d[2]), "+f"(d[3])
        : "r"(a[0]), "r"(a[1]), "r"(a[2]), "r"(a[3]), "r"(b[0]), "r"(b[1]));
}

// ---------------- kernel 1: features (split bf16) ----------------
__global__ void feat_kernel(const float* __restrict__ x)
{
    int idx = blockIdx.x * blockDim.x + threadIdx.x;
    int c  = idx & 63;
    int r  = idx >> 6;
    int wp = r % WP; r /= WP;
    int hp = r % HP;
    int b  = r / HP;

    int h = hp - 1, w = wp - 1;
    float v = 0.0f;
    if (h >= 0 && h < 64 && w >= 0 && w < 64)
        v = x[(((size_t)b*64 + h)*64 + w)*64 + c];

    const float hh = 2.0f / 3.0f;
    float g[10];
    #pragma unroll
    for (int j = 0; j < 10; j++) g[j] = (float)(j - 3) * hh - 1.0f;

    float bas[9];
    #pragma unroll
    for (int i = 0; i < 9; i++)
        bas[i] = (v >= g[i] && v < g[i+1]) ? 1.0f : 0.0f;
    const float rp1 = 1.5f, rp2 = 0.75f, rp3 = 0.5f;   // 1/(p*h), uniform knots
    #pragma unroll
    for (int i = 0; i < 8; i++)
        bas[i] = (v - g[i]) * rp1 * bas[i] + (g[i+2] - v) * rp1 * bas[i+1];
    #pragma unroll
    for (int i = 0; i < 7; i++)
        bas[i] = (v - g[i]) * rp2 * bas[i] + (g[i+3] - v) * rp2 * bas[i+1];
    #pragma unroll
    for (int i = 0; i < 6; i++)
        bas[i] = (v - g[i]) * rp3 * bas[i] + (g[i+4] - v) * rp3 * bas[i+1];

    float s = v / (1.0f + __expf(-v));   // silu

    float f[7] = {s, bas[0], bas[1], bas[2], bas[3], bas[4], bas[5]};
    size_t base = (((size_t)b*HP + hp)*WP + wp)*FDIM + c;
    #pragma unroll
    for (int m = 0; m < 7; m++) {
        float val = f[m];
        __nv_bfloat16 hi = __float2bfloat16(val);
        __nv_bfloat16 lo = __float2bfloat16(val - __bfloat162float(hi));
        g_Fh[base + (size_t)m*64] = hi;
        g_Fl[base + (size_t)m*64] = lo;
    }
}

// ---------------- kernel 2: weight repack + split ----------------
// g_W*[o][k], k = t*448 + f*64 + cin; patch index i = cin*9 + t
__global__ void pack_kernel(const float* __restrict__ base_w,
                            const float* __restrict__ spline_w)
{
    int idx = blockIdx.x * blockDim.x + threadIdx.x;   // o*4032 + k
    if (idx >= COUT * KDIM) return;
    int o = idx / KDIM;
    int k = idx - o * KDIM;
    int t = k / FDIM;
    int rr = k - t * FDIM;
    int f  = rr >> 6;
    int cc = rr & 63;
    int i  = cc * 9 + t;
    float wv = (f == 0) ? base_w[(size_t)o * PATCH + i]
                        : spline_w[((size_t)o * PATCH + i) * 6 + (f - 1)];
    __nv_bfloat16 hi = __float2bfloat16(wv);
    __nv_bfloat16 lo = __float2bfloat16(wv - __bfloat162float(hi));
    g_Wh[idx] = hi;
    g_Wl[idx] = lo;
}

// ---------------- kernel 3: mma.sync bf16 GEMM ----------------
// 256 CTAs x 256 threads. CTA tile: M=128, N=128, K=4032.
// D = Ah*Bh + Ah*Bl + Al*Bh  (split bf16, fp32 register accumulation).
// SMEM tiles: 128 rows x 32 k (64B data, 80B pitch -> conflict-free LDSM).
#define NSTAGE 3
#define PITCH  80
#define TILEB  (128*PITCH)                 // 10240 B
#define STAGEB (4*TILEB)                   // Ah Al Bh Bl = 40960 B
#define DYN_SMEM (NSTAGE*STAGEB)           // 122880 B

__global__ void __launch_bounds__(256, 1)
gemm_kernel(const float* __restrict__ bias, float* __restrict__ out)
{
    extern __shared__ char dyn[];
    const uint32_t smbase = smem_u32(dyn);

    const int tid    = threadIdx.x;
    const int wid    = tid >> 5;
    const int lane   = tid & 31;
    const int warp_m = wid & 3;            // 4 warps along M (32 rows each)
    const int warp_n = wid >> 2;           // 2 warps along N (64 cols each)

    const int pixBase = blockIdx.x * 128;
    const int bimg    = pixBase >> 12;
    const int h0      = (pixBase >> 6) & 63;

    // ---- per-thread cp.async source/dest geometry ----
    const int rrow  = tid >> 1;            // tile row 0..127
    const int halfe = (tid & 1) * 16;      // element offset within 32-elem row
    const int hA    = h0 + (rrow >> 6);
    const int wA    = rrow & 63;
    const size_t baseA = (((size_t)bimg*HP + hA)*WP + wA)*FDIM + halfe;
    const size_t baseB = (size_t)rrow * KDIM + halfe;
    const uint32_t dstRow = smbase + rrow * PITCH + (tid & 1) * 32;

    // ---- per-thread ldmatrix geometry ----
    // A: lanes 0-7 m0-7 k0 | 8-15 m8-15 k0 | 16-23 m0-7 k8 | 24-31 m8-15 k8
    const uint32_t pA = smbase + (warp_m*32 + (lane & 15)) * PITCH + (lane >> 4) * 16;
    // B: lanes 0-7 n0-7 k0 | 8-15 n0-7 k8 | 16-23 n8-15 k0 | 24-31 n8-15 k8
    const uint32_t pB = smbase + 2*TILEB
                      + (warp_n*64 + ((lane >> 4) << 3) + (lane & 7)) * PITCH
                      + ((lane >> 3) & 1) * 16;

    float acc[2][8][4];
    #pragma unroll
    for (int mt = 0; mt < 2; mt++)
        #pragma unroll
        for (int nt = 0; nt < 8; nt++)
            #pragma unroll
            for (int q = 0; q < 4; q++) acc[mt][nt][q] = 0.0f;

    auto produce = [&](int c, int slot) {
        const int t  = c / 14;
        const int rr = c - t * 14;
        const int f  = rr >> 1;
        const int c0 = (rr & 1) << 5;
        const int ky = t / 3;
        const int kx = t - ky * 3;
        const size_t offA = baseA + ((size_t)ky*WP + kx)*FDIM + f*64 + c0;
        const size_t offB = baseB + (size_t)c * 32;
        const uint32_t d  = dstRow + slot * STAGEB;
        cpasync16(d,                 g_Fh + offA);
        cpasync16(d + 16,            g_Fh + offA + 8);
        cpasync16(d + TILEB,         g_Fl + offA);
        cpasync16(d + TILEB + 16,    g_Fl + offA + 8);
        cpasync16(d + 2*TILEB,       g_Wh + offB);
        cpasync16(d + 2*TILEB + 16,  g_Wh + offB + 8);
        cpasync16(d + 3*TILEB,       g_Wl + offB);
        cpasync16(d + 3*TILEB + 16,  g_Wl + offB + 8);
    };

    // prologue: stages 0,1
    produce(0, 0); cp_commit();
    produce(1, 1); cp_commit();

    for (int i = 0; i < NCHUNK; i++) {
        const int cn = i + 2;
        if (cn < NCHUNK) produce(cn, cn % NSTAGE);
        cp_commit();
        cp_wait2();
        __syncthreads();

        const uint32_t so = (i % NSTAGE) * STAGEB;
        #pragma unroll
        for (int kk = 0; kk < 2; kk++) {
            uint32_t ah[2][4], al[2][4];
            #pragma unroll
            for (int mt = 0; mt < 2; mt++) {
                ldsm4(ah[mt], pA + so + mt*16*PITCH + kk*32);
                ldsm4(al[mt], pA + so + TILEB + mt*16*PITCH + kk*32);
            }
            uint32_t bh[8][2], bl[8][2];
            #pragma unroll
            for (int np = 0; np < 4; np++) {
                uint32_t r4[4];
                ldsm4(r4, pB + so + np*16*PITCH + kk*32);
                bh[2*np][0] = r4[0]; bh[2*np][1] = r4[1];
                bh[2*np+1][0] = r4[2]; bh[2*np+1][1] = r4[3];
                ldsm4(r4, pB + so + TILEB + np*16*PITCH + kk*32);
                bl[2*np][0] = r4[0]; bl[2*np][1] = r4[1];
                bl[2*np+1][0] = r4[2]; bl[2*np+1][1] = r4[3];
            }
            #pragma unroll
            for (int mt = 0; mt < 2; mt++)
                #pragma unroll
                for (int nt = 0; nt < 8; nt++) {
                    mma16816(acc[mt][nt], ah[mt], bh[nt]);
                    mma16816(acc[mt][nt], ah[mt], bl[nt]);
                    mma16816(acc[mt][nt], al[mt], bh[nt]);
                }
        }
        __syncthreads();
    }

    // ---- epilogue: + bias, store fp32 ----
    const int prow = pixBase + warp_m*32 + (lane >> 2);
    const int colb = warp_n*64 + (lane & 3)*2;
    #pragma unroll
    for (int nt = 0; nt < 8; nt++) {
        const float2 b2 = *(const float2*)(bias + colb + nt*8);
        #pragma unroll
        for (int mt = 0; mt < 2; mt++) {
            float2 v0, v1;
            v0.x = acc[mt][nt][0] + b2.x;  v0.y = acc[mt][nt][1] + b2.y;
            v1.x = acc[mt][nt][2] + b2.x;  v1.y = acc[mt][nt][3] + b2.y;
            *(float2*)(out + (size_t)(prow + mt*16    )*COUT + colb + nt*8) = v0;
            *(float2*)(out + (size_t)(prow + mt*16 + 8)*COUT + colb + nt*8) = v1;
        }
    }
}

// ---------------- launch ----------------
extern "C" void kernel_launch(void* const* d_in, const int* in_sizes, int n_in,
                              void* d_out, int out_size)
{
    const float *x = nullptr, *bw = nullptr, *sw = nullptr, *bs = nullptr;
    for (int i = 0; i < n_in; i++) {
        switch (in_sizes[i]) {
            case 8*64*64*64:   x  = (const float*)d_in[i]; break;
            case COUT*PATCH:   bw = (const float*)d_in[i]; break;
            case COUT*PATCH*6: sw = (const float*)d_in[i]; break;
            case COUT:         bs = (const float*)d_in[i]; break;
        }
    }
    float* out = (float*)d_out;

    static bool attrDone = false;
    if (!attrDone) {
        cudaFuncSetAttribute(gemm_kernel,
                             cudaFuncAttributeMaxDynamicSharedMemorySize, DYN_SMEM);
        attrDone = true;
    }

    const int featTotal = B_ * HP * WP * CIN;      // 2,230,272
    feat_kernel<<<featTotal / 256, 256>>>(x);

    const int packTotal = COUT * KDIM;             // 516,096
    pack_kernel<<<(packTotal + 255) / 256, 256>>>(bw, sw);

    gemm_kernel<<<NPIX / 128, 256, DYN_SMEM>>>(bs, out);
}

// round 4
// speedup vs baseline: 3.1727x; 1.6090x over previous
#include <cuda_runtime.h>
#include <cuda_fp16.h>
#include <cstdint>

// ---------------- problem constants ----------------
#define B_     8
#define CIN    64
#define COUT   128
#define HP     66
#define WP     66
#define FDIM   448               // 64 ch * 7 features
#define KDIM   4032              // 9 taps * 448
#define NPIX   32768
#define PATCH  576
#define NCHUNK 126               // K chunks of 32

// ---------------- scratch (device globals) ----------------
__device__ __half g_Fh[(size_t)B_*HP*WP*FDIM];   // 31.2 MB  fp16 hi
__device__ __half g_Fl[(size_t)B_*HP*WP*FDIM];   // 31.2 MB  fp16 residual
__device__ __half g_Wf[(size_t)COUT*KDIM];       // 1 MB     fp16 weights [o][k]

// ---------------- PTX helpers ----------------
__device__ __forceinline__ uint32_t smem_u32(const void* p) {
    uint32_t a;
    asm("{ .reg .u64 t; cvta.to.shared.u64 t, %1; cvt.u32.u64 %0, t; }"
        : "=r"(a) : "l"(p));
    return a;
}
__device__ __forceinline__ void cpasync16(uint32_t sa, const void* g) {
    asm volatile("cp.async.cg.shared.global [%0], [%1], 16;"
                 :: "r"(sa), "l"(g) : "memory");
}
__device__ __forceinline__ void cp_commit() {
    asm volatile("cp.async.commit_group;" ::: "memory");
}
__device__ __forceinline__ void cp_wait2() {
    asm volatile("cp.async.wait_group 2;" ::: "memory");
}
__device__ __forceinline__ void ldsm4(uint32_t* r, uint32_t addr) {
    asm volatile("ldmatrix.sync.aligned.m8n8.x4.shared.b16 {%0,%1,%2,%3}, [%4];"
                 : "=r"(r[0]), "=r"(r[1]), "=r"(r[2]), "=r"(r[3]) : "r"(addr));
}
__device__ __forceinline__ void mma16816(float* d, const uint32_t* a, const uint32_t* b) {
    asm volatile(
        "mma.sync.aligned.m16n8k16.row.col.f32.f16.f16.f32 "
        "{%0,%1,%2,%3}, {%4,%5,%6,%7}, {%8,%9}, {%0,%1,%2,%3};"
        : "+f"(d[0]), "+f"(d[1]), "+f"(d[2]), "+f"(d[3])
        : "r"(a[0]), "r"(a[1]), "r"(a[2]), "r"(a[3]), "r"(b[0]), "r"(b[1]));
}

// ---------------- kernel 1: features (split fp16) ----------------
__global__ void feat_kernel(const float* __restrict__ x)
{
    int idx = blockIdx.x * blockDim.x + threadIdx.x;
    int c  = idx & 63;
    int r  = idx >> 6;
    int wp = r % WP; r /= WP;
    int hp = r % HP;
    int b  = r / HP;

    int h = hp - 1, w = wp - 1;
    float v = 0.0f;
    if (h >= 0 && h < 64 && w >= 0 && w < 64)
        v = x[(((size_t)b*64 + h)*64 + w)*64 + c];

    const float hh = 2.0f / 3.0f;
    float g[10];
    #pragma unroll
    for (int j = 0; j < 10; j++) g[j] = (float)(j - 3) * hh - 1.0f;

    float bas[9];
    #pragma unroll
    for (int i = 0; i < 9; i++)
        bas[i] = (v >= g[i] && v < g[i+1]) ? 1.0f : 0.0f;
    const float rp1 = 1.5f, rp2 = 0.75f, rp3 = 0.5f;   // 1/(p*h), uniform knots
    #pragma unroll
    for (int i = 0; i < 8; i++)
        bas[i] = (v - g[i]) * rp1 * bas[i] + (g[i+2] - v) * rp1 * bas[i+1];
    #pragma unroll
    for (int i = 0; i < 7; i++)
        bas[i] = (v - g[i]) * rp2 * bas[i] + (g[i+3] - v) * rp2 * bas[i+1];
    #pragma unroll
    for (int i = 0; i < 6; i++)
        bas[i] = (v - g[i]) * rp3 * bas[i] + (g[i+4] - v) * rp3 * bas[i+1];

    float s = v / (1.0f + __expf(-v));   // silu

    float f[7] = {s, bas[0], bas[1], bas[2], bas[3], bas[4], bas[5]};
    size_t base = (((size_t)b*HP + hp)*WP + wp)*FDIM + c;
    #pragma unroll
    for (int m = 0; m < 7; m++) {
        float val = f[m];
        __half hi = __float2half(val);
        __half lo = __float2half(val - __half2float(hi));
        g_Fh[base + (size_t)m*64] = hi;
        g_Fl[base + (size_t)m*64] = lo;
    }
}

// ---------------- kernel 2: weight repack (fp16) ----------------
// g_Wf[o][k], k = t*448 + f*64 + cin; patch index i = cin*9 + t
__global__ void pack_kernel(const float* __restrict__ base_w,
                            const float* __restrict__ spline_w)
{
    int idx = blockIdx.x * blockDim.x + threadIdx.x;   // o*4032 + k
    if (idx >= COUT * KDIM) return;
    int o = idx / KDIM;
    int k = idx - o * KDIM;
    int t = k / FDIM;
    int rr = k - t * FDIM;
    int f  = rr >> 6;
    int cc = rr & 63;
    int i  = cc * 9 + t;
    float wv = (f == 0) ? base_w[(size_t)o * PATCH + i]
                        : spline_w[((size_t)o * PATCH + i) * 6 + (f - 1)];
    g_Wf[idx] = __float2half(wv);
}

// ---------------- kernel 3: mma.sync fp16 GEMM ----------------
// 256 CTAs x 256 threads, 2 CTAs/SM. CTA tile: M=128, N=128, K=4032.
// D = Ah*B + Al*B  (fp16 2-product split, fp32 register accumulation).
// SMEM tiles: 128 rows x 32 k (64B data, 80B pitch -> conflict-free LDSM).
#define NSTAGE 3
#define PITCH  80
#define TILEB  (128*PITCH)                 // 10240 B
#define STAGEB (3*TILEB)                   // Ah Al B = 30720 B
#define DYN_SMEM (NSTAGE*STAGEB)           // 92160 B  (x2 CTAs = 180 KB/SM)

__global__ void __launch_bounds__(256, 2)
gemm_kernel(const float* __restrict__ bias, float* __restrict__ out)
{
    extern __shared__ char dyn[];
    const uint32_t smbase = smem_u32(dyn);

    const int tid    = threadIdx.x;
    const int wid    = tid >> 5;
    const int lane   = tid & 31;
    const int warp_m = wid & 3;            // 4 warps along M (32 rows each)
    const int warp_n = wid >> 2;           // 2 warps along N (64 cols each)

    const int pixBase = blockIdx.x * 128;
    const int bimg    = pixBase >> 12;
    const int h0      = (pixBase >> 6) & 63;

    // ---- per-thread cp.async source/dest geometry ----
    const int rrow  = tid >> 1;            // tile row 0..127
    const int halfe = (tid & 1) * 16;      // element offset within 32-elem row
    const int hA    = h0 + (rrow >> 6);
    const int wA    = rrow & 63;
    const size_t baseA = (((size_t)bimg*HP + hA)*WP + wA)*FDIM + halfe;
    const size_t baseB = (size_t)rrow * KDIM + halfe;
    const uint32_t dstRow = smbase + rrow * PITCH + (tid & 1) * 32;

    // ---- per-thread ldmatrix geometry ----
    const uint32_t pA = smbase + (warp_m*32 + (lane & 15)) * PITCH + (lane >> 4) * 16;
    const uint32_t pB = smbase + 2*TILEB
                      + (warp_n*64 + ((lane >> 4) << 3) + (lane & 7)) * PITCH
                      + ((lane >> 3) & 1) * 16;

    float acc[2][8][4];
    #pragma unroll
    for (int mt = 0; mt < 2; mt++)
        #pragma unroll
        for (int nt = 0; nt < 8; nt++)
            #pragma unroll
            for (int q = 0; q < 4; q++) acc[mt][nt][q] = 0.0f;

    auto produce = [&](int c, int slot) {
        const int t  = c / 14;
        const int rr = c - t * 14;
        const int f  = rr >> 1;
        const int c0 = (rr & 1) << 5;
        const int ky = t / 3;
        const int kx = t - ky * 3;
        const size_t offA = baseA + ((size_t)ky*WP + kx)*FDIM + f*64 + c0;
        const size_t offB = baseB + (size_t)c * 32;
        const uint32_t d  = dstRow + slot * STAGEB;
        cpasync16(d,                g_Fh + offA);
        cpasync16(d + 16,           g_Fh + offA + 8);
        cpasync16(d + TILEB,        g_Fl + offA);
        cpasync16(d + TILEB + 16,   g_Fl + offA + 8);
        cpasync16(d + 2*TILEB,      g_Wf + offB);
        cpasync16(d + 2*TILEB + 16, g_Wf + offB + 8);
    };

    // prologue: stages 0,1
    produce(0, 0); cp_commit();
    produce(1, 1); cp_commit();

    for (int i = 0; i < NCHUNK; i++) {
        const int cn = i + 2;
        if (cn < NCHUNK) produce(cn, cn % NSTAGE);
        cp_commit();
        cp_wait2();
        __syncthreads();

        const uint32_t so = (i % NSTAGE) * STAGEB;
        #pragma unroll
        for (int kk = 0; kk < 2; kk++) {
            uint32_t ah[2][4], al[2][4];
            #pragma unroll
            for (int mt = 0; mt < 2; mt++) {
                ldsm4(ah[mt], pA + so + mt*16*PITCH + kk*32);
                ldsm4(al[mt], pA + so + TILEB + mt*16*PITCH + kk*32);
            }
            uint32_t bh[8][2];
            #pragma unroll
            for (int np = 0; np < 4; np++) {
                uint32_t r4[4];
                ldsm4(r4, pB + so + np*16*PITCH + kk*32);
                bh[2*np][0] = r4[0];   bh[2*np][1] = r4[1];
                bh[2*np+1][0] = r4[2]; bh[2*np+1][1] = r4[3];
            }
            #pragma unroll
            for (int mt = 0; mt < 2; mt++)
                #pragma unroll
                for (int nt = 0; nt < 8; nt++) {
                    mma16816(acc[mt][nt], ah[mt], bh[nt]);
                    mma16816(acc[mt][nt], al[mt], bh[nt]);
                }
        }
        __syncthreads();
    }

    // ---- epilogue: + bias, store fp32 ----
    const int prow = pixBase + warp_m*32 + (lane >> 2);
    const int colb = warp_n*64 + (lane & 3)*2;
    #pragma unroll
    for (int nt = 0; nt < 8; nt++) {
        const float2 b2 = *(const float2*)(bias + colb + nt*8);
        #pragma unroll
        for (int mt = 0; mt < 2; mt++) {
            float2 v0, v1;
            v0.x = acc[mt][nt][0] + b2.x;  v0.y = acc[mt][nt][1] + b2.y;
            v1.x = acc[mt][nt][2] + b2.x;  v1.y = acc[mt][nt][3] + b2.y;
            *(float2*)(out + (size_t)(prow + mt*16    )*COUT + colb + nt*8) = v0;
            *(float2*)(out + (size_t)(prow + mt*16 + 8)*COUT + colb + nt*8) = v1;
        }
    }
}

// ---------------- launch ----------------
extern "C" void kernel_launch(void* const* d_in, const int* in_sizes, int n_in,
                              void* d_out, int out_size)
{
    const float *x = nullptr, *bw = nullptr, *sw = nullptr, *bs = nullptr;
    for (int i = 0; i < n_in; i++) {
        switch (in_sizes[i]) {
            case 8*64*64*64:   x  = (const float*)d_in[i]; break;
            case COUT*PATCH:   bw = (const float*)d_in[i]; break;
            case COUT*PATCH*6: sw = (const float*)d_in[i]; break;
            case COUT:         bs = (const float*)d_in[i]; break;
        }
    }
    float* out = (float*)d_out;

    static bool attrDone = false;
    if (!attrDone) {
        cudaFuncSetAttribute(gemm_kernel,
                             cudaFuncAttributeMaxDynamicSharedMemorySize, DYN_SMEM);
        attrDone = true;
    }

    const int featTotal = B_ * HP * WP * CIN;      // 2,230,272
    feat_kernel<<<featTotal / 256, 256>>>(x);

    const int packTotal = COUT * KDIM;             // 516,096
    pack_kernel<<<(packTotal + 255) / 256, 256>>>(bw, sw);

    gemm_kernel<<<NPIX / 128, 256, DYN_SMEM>>>(bs, out);
}

// round 5
// speedup vs baseline: 5.0161x; 1.5810x over previous
#include <cuda_runtime.h>
#include <cuda_fp16.h>
#include <cstdint>

// ---------------- problem constants ----------------
#define B_     8
#define CIN    64
#define COUT   128
#define HP     66
#define WP     66
#define FDIM   448               // 64 ch * 7 features
#define KDIM   4032              // 9 taps * 448
#define NPIX   32768
#define PATCH  576
#define NCHUNK 126               // K chunks of 32

// ---------------- scratch (device globals) ----------------
__device__ __half g_Fh[(size_t)B_*HP*WP*FDIM];   // 31.2 MB fp16 features
__device__ __half g_Wf[(size_t)COUT*KDIM];       // 1 MB    fp16 weights [o][k]

// ---------------- PTX helpers ----------------
__device__ __forceinline__ uint32_t smem_u32(const void* p) {
    uint32_t a;
    asm("{ .reg .u64 t; cvta.to.shared.u64 t, %1; cvt.u32.u64 %0, t; }"
        : "=r"(a) : "l"(p));
    return a;
}
__device__ __forceinline__ void cpasync16(uint32_t sa, const void* g) {
    asm volatile("cp.async.cg.shared.global [%0], [%1], 16;"
                 :: "r"(sa), "l"(g) : "memory");
}
__device__ __forceinline__ void cp_commit() {
    asm volatile("cp.async.commit_group;" ::: "memory");
}
__device__ __forceinline__ void cp_wait3() {
    asm volatile("cp.async.wait_group 3;" ::: "memory");
}
__device__ __forceinline__ void ldsm4(uint32_t* r, uint32_t addr) {
    asm volatile("ldmatrix.sync.aligned.m8n8.x4.shared.b16 {%0,%1,%2,%3}, [%4];"
                 : "=r"(r[0]), "=r"(r[1]), "=r"(r[2]), "=r"(r[3]) : "r"(addr));
}
__device__ __forceinline__ void mma16816(float* d, const uint32_t* a, const uint32_t* b) {
    asm volatile(
        "mma.sync.aligned.m16n8k16.row.col.f32.f16.f16.f32 "
        "{%0,%1,%2,%3}, {%4,%5,%6,%7}, {%8,%9}, {%0,%1,%2,%3};"
        : "+f"(d[0]), "+f"(d[1]), "+f"(d[2]), "+f"(d[3])
        : "r"(a[0]), "r"(a[1]), "r"(a[2]), "r"(a[3]), "r"(b[0]), "r"(b[1]));
}

// ---------------- kernel 1: features (fp16) ----------------
__global__ void feat_kernel(const float* __restrict__ x)
{
    int idx = blockIdx.x * blockDim.x + threadIdx.x;
    int c  = idx & 63;
    int r  = idx >> 6;
    int wp = r % WP; r /= WP;
    int hp = r % HP;
    int b  = r / HP;

    int h = hp - 1, w = wp - 1;
    float v = 0.0f;
    if (h >= 0 && h < 64 && w >= 0 && w < 64)
        v = x[(((size_t)b*64 + h)*64 + w)*64 + c];

    const float hh = 2.0f / 3.0f;
    float g[10];
    #pragma unroll
    for (int j = 0; j < 10; j++) g[j] = (float)(j - 3) * hh - 1.0f;

    float bas[9];
    #pragma unroll
    for (int i = 0; i < 9; i++)
        bas[i] = (v >= g[i] && v < g[i+1]) ? 1.0f : 0.0f;
    const float rp1 = 1.5f, rp2 = 0.75f, rp3 = 0.5f;   // 1/(p*h), uniform knots
    #pragma unroll
    for (int i = 0; i < 8; i++)
        bas[i] = (v - g[i]) * rp1 * bas[i] + (g[i+2] - v) * rp1 * bas[i+1];
    #pragma unroll
    for (int i = 0; i < 7; i++)
        bas[i] = (v - g[i]) * rp2 * bas[i] + (g[i+3] - v) * rp2 * bas[i+1];
    #pragma unroll
    for (int i = 0; i < 6; i++)
        bas[i] = (v - g[i]) * rp3 * bas[i] + (g[i+4] - v) * rp3 * bas[i+1];

    float s = v / (1.0f + __expf(-v));   // silu

    float f[7] = {s, bas[0], bas[1], bas[2], bas[3], bas[4], bas[5]};
    size_t base = (((size_t)b*HP + hp)*WP + wp)*FDIM + c;
    #pragma unroll
    for (int m = 0; m < 7; m++)
        g_Fh[base + (size_t)m*64] = __float2half(f[m]);
}

// ---------------- kernel 2: weight repack (fp16) ----------------
// g_Wf[o][k], k = t*448 + f*64 + cin; patch index i = cin*9 + t
__global__ void pack_kernel(const float* __restrict__ base_w,
                            const float* __restrict__ spline_w)
{
    int idx = blockIdx.x * blockDim.x + threadIdx.x;   // o*4032 + k
    if (idx >= COUT * KDIM) return;
    int o = idx / KDIM;
    int k = idx - o * KDIM;
    int t = k / FDIM;
    int rr = k - t * FDIM;
    int f  = rr >> 6;
    int cc = rr & 63;
    int i  = cc * 9 + t;
    float wv = (f == 0) ? base_w[(size_t)o * PATCH + i]
                        : spline_w[((size_t)o * PATCH + i) * 6 + (f - 1)];
    g_Wf[idx] = __float2half(wv);
}

// ---------------- kernel 3: mma.sync fp16 GEMM ----------------
// 256 CTAs x 256 threads, 2 CTAs/SM. CTA tile: M=128, N=128, K=4032.
// Single fp16 product, fp32 register accumulation.
// SMEM tiles: 128 rows x 32 k (64B data, 80B pitch -> conflict-free LDSM).
#define NSTAGE 4
#define PITCH  80
#define TILEB  (128*PITCH)                 // 10240 B
#define STAGEB (2*TILEB)                   // A B = 20480 B
#define DYN_SMEM (NSTAGE*STAGEB)           // 81920 B  (x2 CTAs = 160 KB/SM)

__global__ void __launch_bounds__(256, 2)
gemm_kernel(const float* __restrict__ bias, float* __restrict__ out)
{
    extern __shared__ char dyn[];
    const uint32_t smbase = smem_u32(dyn);

    const int tid    = threadIdx.x;
    const int wid    = tid >> 5;
    const int lane   = tid & 31;
    const int warp_m = wid & 3;            // 4 warps along M (32 rows each)
    const int warp_n = wid >> 2;           // 2 warps along N (64 cols each)

    const int pixBase = blockIdx.x * 128;
    const int bimg    = pixBase >> 12;
    const int h0      = (pixBase >> 6) & 63;

    // ---- per-thread cp.async source/dest geometry ----
    const int rrow  = tid >> 1;            // tile row 0..127
    const int halfe = (tid & 1) * 16;      // element offset within 32-elem row
    const int hA    = h0 + (rrow >> 6);
    const int wA    = rrow & 63;
    const size_t baseA = (((size_t)bimg*HP + hA)*WP + wA)*FDIM + halfe;
    const size_t baseB = (size_t)rrow * KDIM + halfe;
    const uint32_t dstRow = smbase + rrow * PITCH + (tid & 1) * 32;

    // ---- per-thread ldmatrix geometry ----
    const uint32_t pA = smbase + (warp_m*32 + (lane & 15)) * PITCH + (lane >> 4) * 16;
    const uint32_t pB = smbase + TILEB
                      + (warp_n*64 + ((lane >> 4) << 3) + (lane & 7)) * PITCH
                      + ((lane >> 3) & 1) * 16;

    float acc[2][8][4];
    #pragma unroll
    for (int mt = 0; mt < 2; mt++)
        #pragma unroll
        for (int nt = 0; nt < 8; nt++)
            #pragma unroll
            for (int q = 0; q < 4; q++) acc[mt][nt][q] = 0.0f;

    auto produce = [&](int c, int slot) {
        const int t  = c / 14;
        const int rr = c - t * 14;
        const int f  = rr >> 1;
        const int c0 = (rr & 1) << 5;
        const int ky = t / 3;
        const int kx = t - ky * 3;
        const size_t offA = baseA + ((size_t)ky*WP + kx)*FDIM + f*64 + c0;
        const size_t offB = baseB + (size_t)c * 32;
        const uint32_t d  = dstRow + slot * STAGEB;
        cpasync16(d,             g_Fh + offA);
        cpasync16(d + 16,        g_Fh + offA + 8);
        cpasync16(d + TILEB,     g_Wf + offB);
        cpasync16(d + TILEB + 16, g_Wf + offB + 8);
    };

    // prologue: stages 0..2
    produce(0, 0); cp_commit();
    produce(1, 1); cp_commit();
    produce(2, 2); cp_commit();

    for (int i = 0; i < NCHUNK; i++) {
        const int cn = i + 3;
        if (cn < NCHUNK) produce(cn, cn & 3);
        cp_commit();
        cp_wait3();
        __syncthreads();

        const uint32_t so = (i & 3) * STAGEB;
        #pragma unroll
        for (int kk = 0; kk < 2; kk++) {
            uint32_t ah[2][4];
            #pragma unroll
            for (int mt = 0; mt < 2; mt++)
                ldsm4(ah[mt], pA + so + mt*16*PITCH + kk*32);
            uint32_t bh[8][2];
            #pragma unroll
            for (int np = 0; np < 4; np++) {
                uint32_t r4[4];
                ldsm4(r4, pB + so + np*16*PITCH + kk*32);
                bh[2*np][0] = r4[0];   bh[2*np][1] = r4[1];
                bh[2*np+1][0] = r4[2]; bh[2*np+1][1] = r4[3];
            }
            #pragma unroll
            for (int mt = 0; mt < 2; mt++)
                #pragma unroll
                for (int nt = 0; nt < 8; nt++)
                    mma16816(acc[mt][nt], ah[mt], bh[nt]);
        }
        __syncthreads();
    }

    // ---- epilogue: + bias, store fp32 ----
    const int prow = pixBase + warp_m*32 + (lane >> 2);
    const int colb = warp_n*64 + (lane & 3)*2;
    #pragma unroll
    for (int nt = 0; nt < 8; nt++) {
        const float2 b2 = *(const float2*)(bias + colb + nt*8);
        #pragma unroll
        for (int mt = 0; mt < 2; mt++) {
            float2 v0, v1;
            v0.x = acc[mt][nt][0] + b2.x;  v0.y = acc[mt][nt][1] + b2.y;
            v1.x = acc[mt][nt][2] + b2.x;  v1.y = acc[mt][nt][3] + b2.y;
            *(float2*)(out + (size_t)(prow + mt*16    )*COUT + colb + nt*8) = v0;
            *(float2*)(out + (size_t)(prow + mt*16 + 8)*COUT + colb + nt*8) = v1;
        }
    }
}

// ---------------- launch ----------------
extern "C" void kernel_launch(void* const* d_in, const int* in_sizes, int n_in,
                              void* d_out, int out_size)
{
    const float *x = nullptr, *bw = nullptr, *sw = nullptr, *bs = nullptr;
    for (int i = 0; i < n_in; i++) {
        switch (in_sizes[i]) {
            case 8*64*64*64:   x  = (const float*)d_in[i]; break;
            case COUT*PATCH:   bw = (const float*)d_in[i]; break;
            case COUT*PATCH*6: sw = (const float*)d_in[i]; break;
            case COUT:         bs = (const float*)d_in[i]; break;
        }
    }
    float* out = (float*)d_out;

    static bool attrDone = false;
    if (!attrDone) {
        cudaFuncSetAttribute(gemm_kernel,
                             cudaFuncAttributeMaxDynamicSharedMemorySize, DYN_SMEM);
        attrDone = true;
    }

    const int featTotal = B_ * HP * WP * CIN;      // 2,230,272
    feat_kernel<<<featTotal / 256, 256>>>(x);

    const int packTotal = COUT * KDIM;             // 516,096
    pack_kernel<<<(packTotal + 255) / 256, 256>>>(bw, sw);

    gemm_kernel<<<NPIX / 128, 256, DYN_SMEM>>>(bs, out);
}

// round 6
// speedup vs baseline: 5.9267x; 1.1815x over previous
#include <cuda_runtime.h>
#include <cuda_fp16.h>
#include <cstdint>

// ---------------- problem constants ----------------
#define B_     8
#define CIN    64
#define COUT   128
#define HP     66
#define WP     66
#define FDIM   448               // 64 ch * 7 features
#define KDIM   4032              // 9 taps * 448
#define NPIX   32768
#define PATCH  576
#define NCHUNK 126               // K chunks of 32

// ---------------- scratch (device globals) ----------------
__device__ __half g_Fh[(size_t)B_*HP*WP*FDIM];       // 31.2 MB fp16 features
__device__ uint4  g_Wp[(size_t)COUT*KDIM/8];         // 1 MB weights in mma-frag order

// ---------------- PTX helpers ----------------
__device__ __forceinline__ uint32_t smem_u32(const void* p) {
    uint32_t a;
    asm("{ .reg .u64 t; cvta.to.shared.u64 t, %1; cvt.u32.u64 %0, t; }"
        : "=r"(a) : "l"(p));
    return a;
}
__device__ __forceinline__ void cpasync16(uint32_t sa, const void* g) {
    asm volatile("cp.async.cg.shared.global [%0], [%1], 16;"
                 :: "r"(sa), "l"(g) : "memory");
}
__device__ __forceinline__ void cp_commit() {
    asm volatile("cp.async.commit_group;" ::: "memory");
}
__device__ __forceinline__ void cp_wait5() {
    asm volatile("cp.async.wait_group 5;" ::: "memory");
}
__device__ __forceinline__ void ldsm4(uint32_t* r, uint32_t addr) {
    asm volatile("ldmatrix.sync.aligned.m8n8.x4.shared.b16 {%0,%1,%2,%3}, [%4];"
                 : "=r"(r[0]), "=r"(r[1]), "=r"(r[2]), "=r"(r[3]) : "r"(addr));
}
__device__ __forceinline__ void mma16816(float* d, const uint32_t* a, uint32_t b0, uint32_t b1) {
    asm volatile(
        "mma.sync.aligned.m16n8k16.row.col.f32.f16.f16.f32 "
        "{%0,%1,%2,%3}, {%4,%5,%6,%7}, {%8,%9}, {%0,%1,%2,%3};"
        : "+f"(d[0]), "+f"(d[1]), "+f"(d[2]), "+f"(d[3])
        : "r"(a[0]), "r"(a[1]), "r"(a[2]), "r"(a[3]), "r"(b0), "r"(b1));
}

// ---------------- b-spline + silu feature evaluation ----------------
__device__ __forceinline__ void eval_features(float v, float* f)
{
    const float hh = 2.0f / 3.0f;
    float g[10];
    #pragma unroll
    for (int j = 0; j < 10; j++) g[j] = (float)(j - 3) * hh - 1.0f;

    float bas[9];
    #pragma unroll
    for (int i = 0; i < 9; i++)
        bas[i] = (v >= g[i] && v < g[i+1]) ? 1.0f : 0.0f;
    const float rp1 = 1.5f, rp2 = 0.75f, rp3 = 0.5f;   // 1/(p*h), uniform knots
    #pragma unroll
    for (int i = 0; i < 8; i++)
        bas[i] = (v - g[i]) * rp1 * bas[i] + (g[i+2] - v) * rp1 * bas[i+1];
    #pragma unroll
    for (int i = 0; i < 7; i++)
        bas[i] = (v - g[i]) * rp2 * bas[i] + (g[i+3] - v) * rp2 * bas[i+1];
    #pragma unroll
    for (int i = 0; i < 6; i++)
        bas[i] = (v - g[i]) * rp3 * bas[i] + (g[i+4] - v) * rp3 * bas[i+1];

    f[0] = v / (1.0f + __expf(-v));   // silu
    #pragma unroll
    for (int m = 0; m < 6; m++) f[m+1] = bas[m];
}

// ---------------- kernel 1: features (fp16, 2 channels/thread) ----------------
__global__ void feat_kernel(const float* __restrict__ x)
{
    int idx = blockIdx.x * blockDim.x + threadIdx.x;   // (pixel, channel-pair)
    int cp = idx & 31;                                 // channel pair 0..31
    int r  = idx >> 5;
    int wp = r % WP; r /= WP;
    int hp = r % HP;
    int b  = r / HP;

    int h = hp - 1, w = wp - 1;
    float v0 = 0.0f, v1 = 0.0f;
    if (h >= 0 && h < 64 && w >= 0 && w < 64) {
        float2 xv = *(const float2*)&x[((((size_t)b*64 + h)*64 + w) << 6) + cp*2];
        v0 = xv.x; v1 = xv.y;
    }

    float f0[7], f1[7];
    eval_features(v0, f0);
    eval_features(v1, f1);

    size_t base = (((size_t)b*HP + hp)*WP + wp)*FDIM + cp*2;
    #pragma unroll
    for (int m = 0; m < 7; m++)
        *(half2*)&g_Fh[base + (size_t)m*64] = __floats2half2_rn(f0[m], f1[m]);
}

// ---------------- kernel 2: weight repack into mma-fragment order ----------------
// dest half index: idx16*8 + pos,
//   idx16 = ((chunk*4 + warp_n)*4 + nt)*32 + lane
//   lane  = (o&7)*4 + (k&7)/2
//   pos   = kk*4 + r*2 + (k&1),  kk=(k>>4)&1, r=(k>>3)&1
//   warp_n = o>>5, nt = (o>>3)&3, chunk = k>>5
__global__ void pack_kernel(const float* __restrict__ base_w,
                            const float* __restrict__ spline_w)
{
    int idx = blockIdx.x * blockDim.x + threadIdx.x;   // o*4032 + k
    if (idx >= COUT * KDIM) return;
    int o = idx / KDIM;
    int k = idx - o * KDIM;
    int t = k / FDIM;
    int rr = k - t * FDIM;
    int f  = rr >> 6;
    int cc = rr & 63;
    int i  = cc * 9 + t;
    float wv = (f == 0) ? base_w[(size_t)o * PATCH + i]
                        : spline_w[((size_t)o * PATCH + i) * 6 + (f - 1)];

    int chunk  = k >> 5;
    int kk     = (k >> 4) & 1;
    int rbit   = (k >> 3) & 1;
    int lane   = ((o & 7) << 2) | ((k & 7) >> 1);
    int pos    = kk * 4 + rbit * 2 + (k & 1);
    int warp_n = o >> 5;
    int nt     = (o >> 3) & 3;
    size_t idx16 = ((size_t)(chunk * 4 + warp_n) * 4 + nt) * 32 + lane;
    ((__half*)g_Wp)[idx16 * 8 + pos] = __float2half(wv);
}

// ---------------- kernel 3: mma.sync fp16 GEMM, B direct from gmem ----------------
// 512 CTAs x 256 threads, 2 CTAs/SM. CTA tile: M=64, N=128, K=4032.
// A staged in smem (6 stages x 5 KB); B fragments LDG.128'd straight to regs.
#define NSTAGE 6
#define PITCH  80
#define STAGEB (64*PITCH)                 // 5120 B
#define DYN_SMEM (NSTAGE*STAGEB)          // 30720 B

__global__ void __launch_bounds__(256, 2)
gemm_kernel(const float* __restrict__ bias, float* __restrict__ out)
{
    extern __shared__ char dyn[];
    const uint32_t smbase = smem_u32(dyn);

    const int tid    = threadIdx.x;
    const int wid    = tid >> 5;
    const int lane   = tid & 31;
    const int warp_m = wid & 1;            // 2 warps along M (32 rows each)
    const int warp_n = wid >> 1;           // 4 warps along N (32 cols each)

    const int pixBase = blockIdx.x * 64;
    const int bimg    = pixBase >> 12;
    const int h0      = (pixBase >> 6) & 63;   // all 64 pixels share (bimg, h0)

    // ---- A cp.async geometry: 1x16B per thread per chunk ----
    const int rrow = tid >> 2;              // tile row (= w) 0..63
    const int seg  = tid & 3;               // 16B segment within 64B row
    const size_t baseA = (((size_t)bimg*HP + h0)*WP + rrow)*FDIM + seg*8;
    const uint32_t dstA = smbase + rrow * PITCH + seg * 16;

    // ---- A ldmatrix geometry ----
    const uint32_t pA = smbase + (warp_m*32 + (lane & 15)) * PITCH + (lane >> 4) * 16;

    // ---- B LDG geometry: g_Wp[((chunk*4+warp_n)*4+nt)*32+lane] (uint4) ----
    const uint4* wpBase = g_Wp + (size_t)warp_n * 128 + lane;

    float acc[2][4][4];
    #pragma unroll
    for (int mt = 0; mt < 2; mt++)
        #pragma unroll
        for (int nt = 0; nt < 4; nt++)
            #pragma unroll
            for (int q = 0; q < 4; q++) acc[mt][nt][q] = 0.0f;

    auto produce = [&](int c, int slot) {
        const int t  = c / 14;
        const int rr = c - t * 14;
        const int f  = rr >> 1;
        const int c0 = (rr & 1) << 5;
        const int ky = t / 3;
        const int kx = t - ky * 3;
        cpasync16(dstA + slot * STAGEB,
                  g_Fh + baseA + ((size_t)ky*WP + kx)*FDIM + f*64 + c0);
    };

    // prologue: A stages 0..4, B chunk 0
    #pragma unroll
    for (int p = 0; p < 5; p++) { produce(p, p); cp_commit(); }

    uint4 bcur[4], bnxt[4];
    #pragma unroll
    for (int nt = 0; nt < 4; nt++) bcur[nt] = wpBase[nt * 32];

    int slot = 0;
    for (int i = 0; i < NCHUNK; i++) {
        const int cn = i + 5;
        int pslot = slot + 5; if (pslot >= NSTAGE) pslot -= NSTAGE;
        if (cn < NCHUNK) produce(cn, pslot);
        cp_commit();
        if (i + 1 < NCHUNK) {
            const uint4* wn = wpBase + (size_t)(i + 1) * 512;
            #pragma unroll
            for (int nt = 0; nt < 4; nt++) bnxt[nt] = wn[nt * 32];
        }
        cp_wait5();
        __syncthreads();

        const uint32_t so = slot * STAGEB;
        uint32_t a0[4], a1[4];
        ldsm4(a0, pA + so);                // mt=0, kk=0
        ldsm4(a1, pA + so + 16*PITCH);     // mt=1, kk=0
        #pragma unroll
        for (int nt = 0; nt < 4; nt++) {
            mma16816(acc[0][nt], a0, bcur[nt].x, bcur[nt].y);
            mma16816(acc[1][nt], a1, bcur[nt].x, bcur[nt].y);
        }
        ldsm4(a0, pA + so + 32);           // mt=0, kk=1
        ldsm4(a1, pA + so + 16*PITCH + 32);// mt=1, kk=1
        #pragma unroll
        for (int nt = 0; nt < 4; nt++) {
            mma16816(acc[0][nt], a0, bcur[nt].z, bcur[nt].w);
            mma16816(acc[1][nt], a1, bcur[nt].z, bcur[nt].w);
        }
        __syncthreads();

        #pragma unroll
        for (int nt = 0; nt < 4; nt++) bcur[nt] = bnxt[nt];
        if (++slot == NSTAGE) slot = 0;
    }

    // ---- epilogue: + bias, store fp32 ----
    const int colb = warp_n*32 + (lane & 3)*2;
    #pragma unroll
    for (int nt = 0; nt < 4; nt++) {
        const float2 b2 = *(const float2*)(bias + colb + nt*8);
        #pragma unroll
        for (int mt = 0; mt < 2; mt++) {
            const int prow = pixBase + warp_m*32 + mt*16 + (lane >> 2);
            float2 v0, v1;
            v0.x = acc[mt][nt][0] + b2.x;  v0.y = acc[mt][nt][1] + b2.y;
            v1.x = acc[mt][nt][2] + b2.x;  v1.y = acc[mt][nt][3] + b2.y;
            *(float2*)(out + (size_t)prow      *COUT + colb + nt*8) = v0;
            *(float2*)(out + (size_t)(prow + 8)*COUT + colb + nt*8) = v1;
        }
    }
}

// ---------------- launch ----------------
extern "C" void kernel_launch(void* const* d_in, const int* in_sizes, int n_in,
                              void* d_out, int out_size)
{
    const float *x = nullptr, *bw = nullptr, *sw = nullptr, *bs = nullptr;
    for (int i = 0; i < n_in; i++) {
        switch (in_sizes[i]) {
            case 8*64*64*64:   x  = (const float*)d_in[i]; break;
            case COUT*PATCH:   bw = (const float*)d_in[i]; break;
            case COUT*PATCH*6: sw = (const float*)d_in[i]; break;
            case COUT:         bs = (const float*)d_in[i]; break;
        }
    }
    float* out = (float*)d_out;

    const int featTotal = B_ * HP * WP * 32;       // 1,115,136 channel-pairs
    feat_kernel<<<featTotal / 256, 256>>>(x);

    const int packTotal = COUT * KDIM;             // 516,096
    pack_kernel<<<(packTotal + 255) / 256, 256>>>(bw, sw);

    gemm_kernel<<<NPIX / 64, 256, DYN_SMEM>>>(bs, out);
}